// round 7
// baseline (speedup 1.0000x reference)
#include <cuda_runtime.h>
#include <cstdint>
#include <cstddef>

// Wigner D matrices per quaternion: D1 = 3x3 (l=1), D2 = 5x5 (l=2).
__device__ float g_D1[16 * 9];
__device__ float g_D2[16 * 25];

// Templated (compile-time d) z-rotation build — fully unrolled, stays in regs.
// Reference order: sin on anti-diagonal first, then cos on diagonal.
template <int D>
__device__ __forceinline__ void zrotT(float ang, float* M) {
#pragma unroll
    for (int x = 0; x < D * D; x++) M[x] = 0.0f;
    const int L = (D - 1) / 2;
#pragma unroll
    for (int i = 0; i < D; i++) {
        float f = (float)(L - i);
        M[i * D + (D - 1 - i)] = sinf(f * ang);
        M[i * D + i]           = cosf(f * ang);
    }
}

template <int D>
__device__ __forceinline__ void matmulT(const float* A, const float* B, float* C) {
#pragma unroll
    for (int i = 0; i < D; i++)
#pragma unroll
        for (int j = 0; j < D; j++) {
            float s = 0.0f;
#pragma unroll
            for (int k = 0; k < D; k++) s = fmaf(A[i * D + k], B[k * D + j], s);
            C[i * D + j] = s;
        }
}

// 32 threads: tid 0..15 build D1 for quat tid; tid 16..31 build D2 for quat tid-16.
__global__ void setup_kernel(const float* __restrict__ q,
                             const float* __restrict__ J1,
                             const float* __restrict__ J2,
                             int T) {
    const int tid = threadIdx.x;
    const int t = tid & 15;
    if (t >= T) return;

    float r = q[4 * t + 0], i = q[4 * t + 1], j = q[4 * t + 2], k = q[4 * t + 3];
    float inv = rsqrtf(r * r + i * i + j * j + k * k);
    r *= inv; i *= inv; j *= inv; k *= inv;
    float two_s = 2.0f / (r * r + i * i + j * j + k * k);

    float M01 = two_s * (i * j - k * r);
    float M21 = two_s * (j * k + i * r);
    float M11 = 1.0f - two_s * (i * i + k * k);
    float M10 = two_s * (i * j + k * r);
    float M12 = two_s * (j * k - i * r);

    float alpha = atan2f(M01, M21);
    float beta  = acosf(fmaxf(-1.0f, fminf(1.0f, M11)));
    float gamma = atan2f(M10, -M12);

    if (tid < 16) {
        float Za[9], Zb[9], Zg[9], t1[9], t2[9];
        zrotT<3>(alpha, Za); zrotT<3>(beta, Zb); zrotT<3>(gamma, Zg);
        float Jl[9];
#pragma unroll
        for (int x = 0; x < 9; x++) Jl[x] = J1[x];
        matmulT<3>(Za, Jl, t1);
        matmulT<3>(t1, Zb, t2);
        matmulT<3>(t2, Jl, t1);
        matmulT<3>(t1, Zg, t2);
#pragma unroll
        for (int x = 0; x < 9; x++) g_D1[t * 9 + x] = t2[x];
    } else {
        float Za[25], Zb[25], Zg[25], t1[25], t2[25];
        zrotT<5>(alpha, Za); zrotT<5>(beta, Zb); zrotT<5>(gamma, Zg);
        float Jl[25];
#pragma unroll
        for (int x = 0; x < 25; x++) Jl[x] = J2[x];
        matmulT<5>(Za, Jl, t1);
        matmulT<5>(t1, Zb, t2);
        matmulT<5>(t2, Jl, t1);
        matmulT<5>(t1, Zg, t2);
#pragma unroll
        for (int x = 0; x < 25; x++) g_D2[t * 25 + x] = t2[x];
    }
}

// One block per 4 points, 128 threads, work-balanced warps:
//   warp0 (lane m=lane): l=0 direct stores (4 points) + l=2 for points 0,1.
//   warp1: l=1, m=lane,    all 4 points.
//   warp2: l=1, m=32+lane, all 4 points.
//   warp3: l=2, m=lane,    points 2,3.
// D rows distributed by one broadcast LDS + __shfl_sync (no per-value LDS).
// l1/l2 outputs staged in double-buffered smem (stride 3/5 = conflict-free),
// one barrier per t, coalesced float4 copy-out by all 128 threads.
__global__ __launch_bounds__(128, 10) void transform_kernel(
        const float* __restrict__ feat,
        float* __restrict__ out,
        int N, int T) {
    __shared__ float sStage[2][1408];   // 4 points x 352 staged channels, x2
    __shared__ float sD1[144];
    __shared__ float sD2[400];

    const int tid = threadIdx.x;
    const int lane = tid & 31;
    const int warp = tid >> 5;
    const int pbase = blockIdx.x * 4;

    for (int x = tid; x < 144; x += 128) sD1[x] = g_D1[x];
    for (int x = tid; x < 400; x += 128) sD2[x] = g_D2[x];

    // Coalesced feature load into smem (aliases stage buffers; barriers fence it).
    float* sF = &sStage[0][0];
    {
        const float4* src = reinterpret_cast<const float4*>(feat + (size_t)pbase * 480);
        float4* dst = reinterpret_cast<float4*>(sF);
        for (int x = tid; x < 480; x += 128) dst[x] = src[x];
    }
    __syncthreads();

    // Register gather (all compile-time indexing).
    float4 f0[4];
    float in1[4][3];
    float in2[2][5];
    if (warp == 0) {
#pragma unroll
        for (int pp = 0; pp < 4; pp++)
            f0[pp] = reinterpret_cast<const float4*>(sF + pp * 480)[lane];
#pragma unroll
        for (int pp = 0; pp < 2; pp++)
#pragma unroll
            for (int b = 0; b < 5; b++)
                in2[pp][b] = sF[pp * 480 + 320 + 5 * lane + b];
    } else if (warp == 3) {
#pragma unroll
        for (int pp = 0; pp < 2; pp++)
#pragma unroll
            for (int b = 0; b < 5; b++)
                in2[pp][b] = sF[(2 + pp) * 480 + 320 + 5 * lane + b];
    } else {
        const int m = (warp - 1) * 32 + lane;
#pragma unroll
        for (int pp = 0; pp < 4; pp++)
#pragma unroll
            for (int b = 0; b < 3; b++)
                in1[pp][b] = sF[pp * 480 + 128 + 3 * m + b];
    }
    __syncthreads();   // done reading sF before first stage write

    for (int t = 0; t < T; t++) {
        float* buf = sStage[t & 1];
        float* obase = out + ((size_t)t * N + pbase) * 480;

        if (warp == 0 || warp == 3) {
            const int ppb = (warp == 0) ? 0 : 2;
            if (warp == 0) {
#pragma unroll
                for (int pp = 0; pp < 4; pp++)
                    reinterpret_cast<float4*>(obase + pp * 480)[lane] = f0[pp];
            }
            float v2 = (lane < 25) ? sD2[t * 25 + lane] : 0.0f;
#pragma unroll
            for (int a = 0; a < 5; a++) {
                const float d0 = __shfl_sync(0xffffffffu, v2, 5 * a + 0);
                const float d1 = __shfl_sync(0xffffffffu, v2, 5 * a + 1);
                const float d2 = __shfl_sync(0xffffffffu, v2, 5 * a + 2);
                const float d3 = __shfl_sync(0xffffffffu, v2, 5 * a + 3);
                const float d4 = __shfl_sync(0xffffffffu, v2, 5 * a + 4);
#pragma unroll
                for (int pp = 0; pp < 2; pp++) {
                    float s = d0 * in2[pp][0];
                    s = fmaf(d1, in2[pp][1], s);
                    s = fmaf(d2, in2[pp][2], s);
                    s = fmaf(d3, in2[pp][3], s);
                    s = fmaf(d4, in2[pp][4], s);
                    buf[(ppb + pp) * 352 + 192 + 5 * lane + a] = s;
                }
            }
        } else {
            const int m = (warp - 1) * 32 + lane;
            float v1 = (lane < 9) ? sD1[t * 9 + lane] : 0.0f;
#pragma unroll
            for (int a = 0; a < 3; a++) {
                const float d0 = __shfl_sync(0xffffffffu, v1, 3 * a + 0);
                const float d1 = __shfl_sync(0xffffffffu, v1, 3 * a + 1);
                const float d2 = __shfl_sync(0xffffffffu, v1, 3 * a + 2);
#pragma unroll
                for (int pp = 0; pp < 4; pp++)
                    buf[pp * 352 + 3 * m + a] =
                        fmaf(d0, in1[pp][0], fmaf(d1, in1[pp][1], d2 * in1[pp][2]));
            }
        }
        __syncthreads();
        // One barrier per t is safe with double buffering: writers of buffer
        // (t&1) at iter t+2 have passed the barrier of iter t+1, which required
        // every thread to finish its iter-t copy-out.

        // Coalesced copy-out: 352 float4 chunks over 128 threads.
#pragma unroll
        for (int x = tid; x < 352; x += 128) {
            const int pp = x / 88;
            const int c4 = x - pp * 88;
            float4 v = reinterpret_cast<const float4*>(buf + pp * 352)[c4];
            reinterpret_cast<float4*>(obase + pp * 480 + 128)[c4] = v;
        }
    }
}

extern "C" void kernel_launch(void* const* d_in, const int* in_sizes, int n_in,
                              void* d_out, int out_size) {
    const float* feat = (const float*)d_in[0];
    const float* q    = (const float*)d_in[1];
    // d_in[2] = J0 (unused: l=0 is a pure broadcast in the reference)
    const float* J1   = (const float*)d_in[3];
    const float* J2   = (const float*)d_in[4];
    float* out = (float*)d_out;

    const int T = in_sizes[1] / 4;     // 16
    const int N = in_sizes[0] / 480;   // 16384

    setup_kernel<<<1, 32>>>(q, J1, J2, T);
    transform_kernel<<<N / 4, 128>>>(feat, out, N, T);
}